// round 1
// baseline (speedup 1.0000x reference)
#include <cuda_runtime.h>
#include <math.h>
#include <stdint.h>

// Problem constants
#define KC 19      // classes
#define MP 10      // prototypes per class
#define CH 720     // channels
#define JN 190     // KC*MP
#define JPAD 192   // padded GEMM N
#define NMAX 65536 // pixels (4*128*128)

// GEMM tiling
#define BM 128
#define BN 192
#define BK 16
#define TM 4
#define TN 12
// 512 threads per GEMM block

// ---------------- scratch (__device__ globals; no allocation) ----------------
__device__ float g_Bt[CH * JPAD];       // normalized protos, [c][j], j = m*19+k
__device__ float g_mu[NMAX];            // per-row mean
__device__ float g_P[NMAX];             // rs * inv_l2norm
__device__ float g_Q[NMAX];             // inv_l2norm
__device__ float g_e[NMAX * MP];        // exp(sim[n,m,g(n)]/eps)
__device__ float g_c[NMAX];             // sinkhorn per-pixel factor
__device__ float g_S[KC];               // per-class initial sum
__device__ int   g_cnt[KC];             // per-class pixel count
__device__ float g_T[JN];               // per-(k,m) column sums
__device__ float g_r[JN];               // sinkhorn per-(k,m) factor

// ---------------- utils ----------------
__device__ __forceinline__ float blockReduceSum(float v, float* sh) {
    __syncthreads();
    #pragma unroll
    for (int o = 16; o > 0; o >>= 1) v += __shfl_down_sync(0xffffffffu, v, o);
    int lane = threadIdx.x & 31, w = threadIdx.x >> 5;
    if (lane == 0) sh[w] = v;
    __syncthreads();
    int nw = (blockDim.x + 31) >> 5;
    v = (threadIdx.x < nw) ? sh[threadIdx.x] : 0.f;
    if (w == 0) {
        #pragma unroll
        for (int o = 16; o > 0; o >>= 1) v += __shfl_down_sync(0xffffffffu, v, o);
        if (lane == 0) sh[0] = v;
    }
    __syncthreads();
    return sh[0];
}

// ---------------- K0: normalize prototypes -> g_Bt; init scalars ----------------
__global__ void kproto(const float* __restrict__ proto) {
    int p = blockIdx.x;
    if (p == JN) {  // init block
        int t = threadIdx.x;
        for (int c = t; c < CH; c += blockDim.x) {
            g_Bt[c * JPAD + 190] = 0.f;
            g_Bt[c * JPAD + 191] = 0.f;
        }
        if (t < KC) { g_S[t] = 0.f; g_cnt[t] = 0; }
        for (int j = t; j < JN; j += blockDim.x) { g_r[j] = 1.f; g_T[j] = 0.f; }
        return;
    }
    int k = p / MP, m = p % MP;
    int j = m * KC + k;                     // output col order so sim is contiguous
    const float* row = proto + (size_t)p * CH;
    __shared__ float sh[32];
    float ss = 0.f;
    for (int c = threadIdx.x; c < CH; c += blockDim.x) { float v = row[c]; ss += v * v; }
    ss = blockReduceSum(ss, sh);
    float inv = 1.f / fmaxf(sqrtf(ss), 1e-12f);
    for (int c = threadIdx.x; c < CH; c += blockDim.x)
        g_Bt[c * JPAD + j] = row[c] * inv;
}

// ---------------- K1: per-row layernorm + l2 stats ----------------
__global__ void kstats(const float* __restrict__ x, const float* __restrict__ gamma,
                       const float* __restrict__ beta, int N) {
    int n = blockIdx.x;
    if (n >= N) return;
    const float* row = x + (size_t)n * CH;
    __shared__ float sh[32];
    float s = 0.f, sq = 0.f;
    for (int c = threadIdx.x; c < CH; c += blockDim.x) { float v = row[c]; s += v; sq += v * v; }
    s = blockReduceSum(s, sh);
    sq = blockReduceSum(sq, sh);
    float mu = s / (float)CH;
    float var = sq / (float)CH - mu * mu;
    float rs = rsqrtf(var + 1e-5f);
    float yn = 0.f;
    for (int c = threadIdx.x; c < CH; c += blockDim.x) {
        float y = (row[c] - mu) * rs * gamma[c] + beta[c];
        yn += y * y;
    }
    yn = blockReduceSum(yn, sh);
    float inv = 1.f / fmaxf(sqrtf(yn), 1e-12f);
    if (threadIdx.x == 0) { g_mu[n] = mu; g_P[n] = rs * inv; g_Q[n] = inv; }
}

// ---------------- K2: GEMM sim[n, j] = xn[n,:] . Bt[:, j] ----------------
__global__ __launch_bounds__(512) void kgemm(const float* __restrict__ x,
                                             const float* __restrict__ gamma,
                                             const float* __restrict__ beta,
                                             float* __restrict__ sim, int N) {
    __shared__ float As[BM * BK];   // [row][kk]
    __shared__ float Bs[BK * BN];   // [kk][col]
    int tid = (int)threadIdx.x;
    int tx = tid & 15;              // 0..15  -> col group of 12
    int ty = tid >> 4;              // 0..31  -> row group of 4
    int rowBase = (int)blockIdx.x * BM;

    float acc[TM][TN];
    #pragma unroll
    for (int i = 0; i < TM; i++)
        #pragma unroll
        for (int jj = 0; jj < TN; jj++) acc[i][jj] = 0.f;

    // A-load assignment: each thread loads one float4 per K-step
    int arow = tid >> 2;            // 0..127
    int akq = tid & 3;              // which float4 of the 16-wide k slice
    int grow = rowBase + arow;
    int srow = grow < N ? grow : 0;
    float mu = g_mu[srow], P = g_P[srow], Q = g_Q[srow];
    const float4* xv = (const float4*)(x + (size_t)srow * CH);
    const float4* gv4 = (const float4*)gamma;
    const float4* bv4 = (const float4*)beta;
    const float4* Btv = (const float4*)g_Bt;

    for (int k0 = 0; k0 < CH; k0 += BK) {
        // load B tile: 768 float4s
        #pragma unroll
        for (int i = 0; i < 2; i++) {
            int idx4 = tid + i * 512;
            if (idx4 < (BK * BN / 4)) {
                int r = idx4 / (BN / 4), c4 = idx4 % (BN / 4);
                ((float4*)Bs)[idx4] = Btv[(size_t)(k0 + r) * (JPAD / 4) + c4];
            }
        }
        // load + transform A tile: 512 float4s
        {
            float4 v = xv[(k0 >> 2) + akq];
            float4 gv = gv4[(k0 >> 2) + akq];
            float4 bv = bv4[(k0 >> 2) + akq];
            float4 a;
            a.x = (v.x - mu) * P * gv.x + Q * bv.x;
            a.y = (v.y - mu) * P * gv.y + Q * bv.y;
            a.z = (v.z - mu) * P * gv.z + Q * bv.z;
            a.w = (v.w - mu) * P * gv.w + Q * bv.w;
            ((float4*)(As + arow * BK))[akq] = a;
        }
        __syncthreads();
        #pragma unroll
        for (int kk = 0; kk < BK; kk++) {
            float bf[TN];
            #pragma unroll
            for (int jj = 0; jj < 3; jj++)
                *(float4*)&bf[jj * 4] = *(const float4*)&Bs[kk * BN + tx * TN + jj * 4];
            float af[TM];
            #pragma unroll
            for (int i = 0; i < TM; i++) af[i] = As[(ty * TM + i) * BK + kk];
            #pragma unroll
            for (int i = 0; i < TM; i++)
                #pragma unroll
                for (int jj = 0; jj < TN; jj++) acc[i][jj] += af[i] * bf[jj];
        }
        __syncthreads();
    }
    #pragma unroll
    for (int i = 0; i < TM; i++) {
        int r = rowBase + ty * TM + i;
        if (r < N) {
            #pragma unroll
            for (int jj = 0; jj < TN; jj++) {
                int c = tx * TN + jj;
                if (c < JN) sim[(size_t)r * JN + c] = acc[i][jj];
            }
        }
    }
}

// ---------------- K3: per-pixel max/argmax, e = exp(sim/eps), class sums ----------------
__global__ void kpix(const float* __restrict__ sim, const int* __restrict__ gt,
                     float* __restrict__ pred_out, int N) {
    __shared__ float sS[KC];
    __shared__ int sC[KC];
    if (threadIdx.x < KC) { sS[threadIdx.x] = 0.f; sC[threadIdx.x] = 0; }
    __syncthreads();
    int n = blockIdx.x * blockDim.x + threadIdx.x;
    if (n < N) {
        const float* row = sim + (size_t)n * JN;
        int g = gt[n];
        float best = -3.4e38f; int bk = 0;
        #pragma unroll
        for (int k = 0; k < KC; k++) {
            float mk = row[k];
            #pragma unroll
            for (int m = 1; m < MP; m++) mk = fmaxf(mk, row[m * KC + k]);
            if (mk > best) { best = mk; bk = k; }   // first-occurrence argmax
        }
        pred_out[n] = (float)bk;
        float se = 0.f;
        #pragma unroll
        for (int m = 0; m < MP; m++) {
            float e = expf(row[m * KC + g] * 20.0f);  // /0.05
            g_e[(size_t)n * MP + m] = e;
            se += e;
        }
        atomicAdd(&sS[g], se);
        atomicAdd(&sC[g], 1);
    }
    __syncthreads();
    if (threadIdx.x < KC) {
        if (sS[threadIdx.x] != 0.f) atomicAdd(&g_S[threadIdx.x], sS[threadIdx.x]);
        if (sC[threadIdx.x] != 0)   atomicAdd(&g_cnt[threadIdx.x], sC[threadIdx.x]);
    }
}

// ---------------- sinkhorn: T accumulation ----------------
template<bool FIRST>
__global__ void kT(const int* __restrict__ gt, int N) {
    __shared__ float sT[JN];
    for (int j = threadIdx.x; j < JN; j += blockDim.x) sT[j] = 0.f;
    __syncthreads();
    for (int n = blockIdx.x * blockDim.x + threadIdx.x; n < N; n += gridDim.x * blockDim.x) {
        int g = gt[n];
        float c;
        if (FIRST) { c = 1.f / fmaxf(g_S[g], 1e-12f); g_c[n] = c; }
        else        c = g_c[n];
        #pragma unroll
        for (int m = 0; m < MP; m++) atomicAdd(&sT[g * MP + m], c * g_e[(size_t)n * MP + m]);
    }
    __syncthreads();
    for (int j = threadIdx.x; j < JN; j += blockDim.x)
        if (sT[j] != 0.f) atomicAdd(&g_T[j], sT[j]);
}

// ---------------- sinkhorn: r update (tiny) ----------------
__global__ void kR() {
    int j = threadIdx.x;
    if (j < JN) {
        float r = g_r[j];
        float T = g_T[j];
        g_r[j] = r / (fmaxf(r * T, 1e-12f) * (float)MP);
        g_T[j] = 0.f;   // ready for next iteration
    }
}

// ---------------- sinkhorn: c update ----------------
__global__ void kC(const int* __restrict__ gt, int N) {
    int n = blockIdx.x * blockDim.x + threadIdx.x;
    if (n >= N) return;
    int g = gt[n];
    float c = g_c[n];
    float V = 0.f;
    #pragma unroll
    for (int m = 0; m < MP; m++) V += g_e[(size_t)n * MP + m] * g_r[g * MP + m];
    float ns = fmaxf((float)g_cnt[g], 1.f);
    g_c[n] = c / (fmaxf(c * V, 1e-12f) * ns);
}

// ---------------- final scatter of q ----------------
__global__ void kQ(const int* __restrict__ gt, float* __restrict__ qout, int N) {
    int n = blockIdx.x * blockDim.x + threadIdx.x;
    if (n >= N) return;
    int g = gt[n];
    float ns = fmaxf((float)g_cnt[g], 1.f);
    float c = g_c[n] * ns;
    size_t base = ((size_t)g * N + n) * MP;
    #pragma unroll
    for (int m = 0; m < MP; m++)
        qout[base + m] = c * g_e[(size_t)n * MP + m] * g_r[g * MP + m];
}

// ---------------- launch ----------------
extern "C" void kernel_launch(void* const* d_in, const int* in_sizes, int n_in,
                              void* d_out, int out_size) {
    const float* x     = (const float*)d_in[0];
    const int*   gt    = (const int*)d_in[1];
    const float* gamma = (const float*)d_in[2];
    const float* beta  = (const float*)d_in[3];
    const float* proto = (const float*)d_in[4];
    int N = in_sizes[0] / CH;

    float* out  = (float*)d_out;
    float* sim  = out;                          // [N, M, K] contiguous (j = m*19+k)
    float* q    = out + (size_t)N * JN;         // [K, N, M]
    float* pred = out + 2 * (size_t)N * JN;     // [N]

    kproto<<<JN + 1, 128>>>(proto);
    kstats<<<N, 128>>>(x, gamma, beta, N);
    kgemm<<<(N + BM - 1) / BM, 512>>>(x, gamma, beta, sim, N);
    kpix<<<(N + 255) / 256, 256>>>(sim, gt, pred, N);

    // 3 sinkhorn iterations, fully factorized
    kT<true><<<256, 256>>>(gt, N);
    kR<<<1, 256>>>();
    kC<<<(N + 255) / 256, 256>>>(gt, N);

    kT<false><<<256, 256>>>(gt, N);
    kR<<<1, 256>>>();
    kC<<<(N + 255) / 256, 256>>>(gt, N);

    kT<false><<<256, 256>>>(gt, N);
    kR<<<1, 256>>>();
    kC<<<(N + 255) / 256, 256>>>(gt, N);

    cudaMemsetAsync(q, 0, (size_t)N * JN * sizeof(float));
    kQ<<<(N + 255) / 256, 256>>>(gt, q, N);
}

// round 3
// speedup vs baseline: 1.8839x; 1.8839x over previous
#include <cuda_runtime.h>
#include <cuda_bf16.h>
#include <math.h>
#include <stdint.h>

// Problem constants
#define KC 19
#define MP 10
#define CH 720
#define CHP 768          // padded K
#define JN 190
#define JP 192           // padded output cols
#define NMAX 65536

// ---------------- scratch (__device__ globals; no allocation) ----------------
__device__ __align__(256) __nv_bfloat16 g_Bhi[JP * CHP];
__device__ __align__(256) __nv_bfloat16 g_Blo[JP * CHP];
__device__ float g_mu[NMAX];
__device__ float g_P[NMAX];
__device__ float g_Q[NMAX];
__device__ float g_e[(size_t)NMAX * MP];
__device__ float g_c[NMAX];
__device__ float g_S[KC];
__device__ int   g_cnt[KC];
__device__ float g_T[JN];
__device__ float g_r[JN];

// ---------------- helpers ----------------
__device__ __forceinline__ uint32_t smem_u32(const void* p) {
    uint32_t a;
    asm("{ .reg .u64 t; cvta.to.shared.u64 t, %1; cvt.u32.u64 %0, t; }" : "=r"(a) : "l"(p));
    return a;
}

__device__ __forceinline__ float blockReduceSum(float v, float* sh) {
    __syncthreads();
    #pragma unroll
    for (int o = 16; o > 0; o >>= 1) v += __shfl_down_sync(0xffffffffu, v, o);
    int lane = threadIdx.x & 31, w = threadIdx.x >> 5;
    if (lane == 0) sh[w] = v;
    __syncthreads();
    int nw = (blockDim.x + 31) >> 5;
    v = (threadIdx.x < nw) ? sh[threadIdx.x] : 0.f;
    if (w == 0) {
        #pragma unroll
        for (int o = 16; o > 0; o >>= 1) v += __shfl_down_sync(0xffffffffu, v, o);
        if (lane == 0) sh[0] = v;
    }
    __syncthreads();
    return sh[0];
}

__device__ __forceinline__ void split2(float a0, float a1, unsigned& h, unsigned& l) {
    __nv_bfloat16 h0 = __float2bfloat16(a0), h1 = __float2bfloat16(a1);
    float r0 = a0 - __bfloat162float(h0), r1 = a1 - __bfloat162float(h1);
    __nv_bfloat16 l0 = __float2bfloat16(r0), l1 = __float2bfloat16(r1);
    h = (unsigned)__bfloat16_as_ushort(h0) | ((unsigned)__bfloat16_as_ushort(h1) << 16);
    l = (unsigned)__bfloat16_as_ushort(l0) | ((unsigned)__bfloat16_as_ushort(l1) << 16);
}

#define LDMX4(r0, r1, r2, r3, addr) \
    asm volatile("ldmatrix.sync.aligned.m8n8.x4.shared.b16 {%0,%1,%2,%3}, [%4];" \
                 : "=r"(r0), "=r"(r1), "=r"(r2), "=r"(r3) : "r"(addr))

#define MMA16816(d, a, b0, b1) \
    asm volatile("mma.sync.aligned.m16n8k16.row.col.f32.bf16.bf16.f32 " \
                 "{%0,%1,%2,%3}, {%4,%5,%6,%7}, {%8,%9}, {%0,%1,%2,%3};" \
                 : "+f"((d)[0]), "+f"((d)[1]), "+f"((d)[2]), "+f"((d)[3]) \
                 : "r"((a)[0]), "r"((a)[1]), "r"((a)[2]), "r"((a)[3]), "r"(b0), "r"(b1))

// ---------------- K0: per-row layernorm + l2 stats -> mu, P, Q ----------------
__global__ __launch_bounds__(256) void kstats(const float* __restrict__ x,
                                              const float* __restrict__ gamma,
                                              const float* __restrict__ beta, int N) {
    int n = blockIdx.x;
    if (n >= N) return;
    int t = threadIdx.x;
    __shared__ float sh[32];
    const float4* xr = (const float4*)(x + (size_t)n * CH);
    float4 v = make_float4(0.f, 0.f, 0.f, 0.f);
    float s = 0.f, sq = 0.f;
    if (t < 180) {
        v = xr[t];
        s = v.x + v.y + v.z + v.w;
        sq = v.x * v.x + v.y * v.y + v.z * v.z + v.w * v.w;
    }
    s = blockReduceSum(s, sh);
    sq = blockReduceSum(sq, sh);
    float mu = s * (1.f / (float)CH);
    float rs = rsqrtf(sq * (1.f / (float)CH) - mu * mu + 1e-5f);
    float yn = 0.f;
    if (t < 180) {
        float4 g4 = ((const float4*)gamma)[t];
        float4 b4 = ((const float4*)beta)[t];
        float a = (v.x - mu) * rs * g4.x + b4.x;
        float b = (v.y - mu) * rs * g4.y + b4.y;
        float c = (v.z - mu) * rs * g4.z + b4.z;
        float d = (v.w - mu) * rs * g4.w + b4.w;
        yn = a * a + b * b + c * c + d * d;
    }
    yn = blockReduceSum(yn, sh);
    float inv = 1.f / fmaxf(sqrtf(yn), 1e-12f);
    if (t == 0) { g_mu[n] = mu; g_P[n] = rs * inv; g_Q[n] = inv; }
}

// ---------------- K1: normalize prototypes -> B hi/lo; init scalars ----------------
__global__ __launch_bounds__(192) void kprotoB(const float* __restrict__ proto) {
    int p = blockIdx.x;
    int t = threadIdx.x;  // 192
    __shared__ float sh[32];
    if (p == JN) {  // pad rows 190/191 + init scalars
        ((uint2*)(g_Bhi + (size_t)190 * CHP))[t] = make_uint2(0u, 0u);
        ((uint2*)(g_Bhi + (size_t)191 * CHP))[t] = make_uint2(0u, 0u);
        ((uint2*)(g_Blo + (size_t)190 * CHP))[t] = make_uint2(0u, 0u);
        ((uint2*)(g_Blo + (size_t)191 * CHP))[t] = make_uint2(0u, 0u);
        if (t < KC) { g_S[t] = 0.f; g_cnt[t] = 0; }
        if (t < JN) { g_r[t] = 1.f; g_T[t] = 0.f; }
        return;
    }
    int k = p / MP, m = p % MP;
    int j = m * KC + k;     // output column order -> sim contiguous [n][m*19+k]
    const float4* pr = (const float4*)(proto + (size_t)p * CH);
    float4 v = make_float4(0.f, 0.f, 0.f, 0.f);
    float ss = 0.f;
    if (t < 180) {
        v = pr[t];
        ss = v.x * v.x + v.y * v.y + v.z * v.z + v.w * v.w;
    }
    ss = blockReduceSum(ss, sh);
    float inv = 1.f / fmaxf(sqrtf(ss), 1e-12f);
    uint2 h = make_uint2(0u, 0u), l = make_uint2(0u, 0u);
    if (t < 180) {
        split2(v.x * inv, v.y * inv, h.x, l.x);
        split2(v.z * inv, v.w * inv, h.y, l.y);
    }
    ((uint2*)(g_Bhi + (size_t)j * CHP))[t] = h;
    ((uint2*)(g_Blo + (size_t)j * CHP))[t] = l;
}

// ---------------- K2: HMMA GEMM, fused layernorm+split, hi/lo 3-product ----------------
// CTA: 256 threads, tile 128(M) x 96(N). Warp tile 32x48. K chunks of 64, 12 chunks.
// SMEM: Ahi 16K @0, Alo 16K @16384, Bhi 12K @32768, Blo 12K @45056  (57344 total)
#define GEMM_SMEM 57344

__global__ __launch_bounds__(256) void kgemm_mma(const float* __restrict__ x,
                                                 const float* __restrict__ gamma,
                                                 const float* __restrict__ beta,
                                                 float* __restrict__ sim, int N) {
    extern __shared__ char smem[];
    const uint32_t sb = smem_u32(smem);
    const uint32_t sAhi = sb, sAlo = sb + 16384, sBhi = sb + 32768, sBlo = sb + 45056;

    int tid = threadIdx.x;
    int lane = tid & 31, warp = tid >> 5;
    int wm = warp & 3, wn = warp >> 2;           // 4 M-warps x 2 N-warps
    int rowBase = (int)blockIdx.x * 128;
    int bnBase = (int)blockIdx.y * 96;

    // A-load assignment: 128 rows x 16 float4; thread covers (tid>>4 + r*16, tid&15)
    int arow = tid >> 4, aq = tid & 15;
    // B-load assignment: 96 rows x 8 uint4; thread covers (tid>>3 + r*32, tid&7)
    int brow = tid >> 3, bq = tid & 7;

    // per-row stats for the 8 A rows this thread converts
    float mu[8], Pv[8], Qv[8];
    #pragma unroll
    for (int r = 0; r < 8; r++) {
        int gr = rowBase + arow + r * 16;
        if (gr < N) { mu[r] = g_mu[gr]; Pv[r] = g_P[gr]; Qv[r] = g_Q[gr]; }
        else        { mu[r] = 0.f; Pv[r] = 0.f; Qv[r] = 0.f; }
    }

    float acc[2][6][4];
    #pragma unroll
    for (int t = 0; t < 2; t++)
        #pragma unroll
        for (int nt = 0; nt < 6; nt++)
            #pragma unroll
            for (int i = 0; i < 4; i++) acc[t][nt][i] = 0.f;

    float4 xr[8];
    float4 g4, b4;
    uint4 bh[3], bl[3];

    // ---- prefetch chunk 0 ----
    {
        int k = aq * 4;
        bool kin = (k < CH);
        g4 = kin ? ((const float4*)gamma)[aq] : make_float4(0, 0, 0, 0);
        b4 = kin ? ((const float4*)beta)[aq]  : make_float4(0, 0, 0, 0);
        #pragma unroll
        for (int r = 0; r < 8; r++) {
            int gr = rowBase + arow + r * 16;
            xr[r] = (kin && gr < N) ? ((const float4*)(x + (size_t)gr * CH))[aq]
                                    : make_float4(0, 0, 0, 0);
        }
        #pragma unroll
        for (int r = 0; r < 3; r++) {
            int gj = bnBase + brow + r * 32;
            bh[r] = ((const uint4*)(g_Bhi + (size_t)gj * CHP))[bq];
            bl[r] = ((const uint4*)(g_Blo + (size_t)gj * CHP))[bq];
        }
    }

    for (int c = 0; c < 12; c++) {
        __syncthreads();   // previous MMA done reading smem
        // ---- convert + store A ----
        #pragma unroll
        for (int r = 0; r < 8; r++) {
            float yx = (xr[r].x - mu[r]) * Pv[r] * g4.x + Qv[r] * b4.x;
            float yy = (xr[r].y - mu[r]) * Pv[r] * g4.y + Qv[r] * b4.y;
            float yz = (xr[r].z - mu[r]) * Pv[r] * g4.z + Qv[r] * b4.z;
            float yw = (xr[r].w - mu[r]) * Pv[r] * g4.w + Qv[r] * b4.w;
            unsigned h0, l0, h1, l1;
            split2(yx, yy, h0, l0);
            split2(yz, yw, h1, l1);
            int row = arow + r * 16;
            uint32_t off = (uint32_t)(row * 128 + ((aq * 8) ^ ((row & 7) << 4)));
            asm volatile("st.shared.v2.b32 [%0], {%1,%2};" :: "r"(sAhi + off), "r"(h0), "r"(h1));
            asm volatile("st.shared.v2.b32 [%0], {%1,%2};" :: "r"(sAlo + off), "r"(l0), "r"(l1));
        }
        // ---- store B ----
        #pragma unroll
        for (int r = 0; r < 3; r++) {
            int row = brow + r * 32;
            uint32_t off = (uint32_t)(row * 128 + ((bq * 16) ^ ((row & 7) << 4)));
            asm volatile("st.shared.v4.b32 [%0], {%1,%2,%3,%4};"
                         :: "r"(sBhi + off), "r"(bh[r].x), "r"(bh[r].y), "r"(bh[r].z), "r"(bh[r].w));
            asm volatile("st.shared.v4.b32 [%0], {%1,%2,%3,%4};"
                         :: "r"(sBlo + off), "r"(bl[r].x), "r"(bl[r].y), "r"(bl[r].z), "r"(bl[r].w));
        }
        __syncthreads();

        // ---- prefetch chunk c+1 (latency hidden under MMA) ----
        if (c < 11) {
            int c0 = (c + 1) * 64;
            int k = c0 + aq * 4;
            bool kin = (k < CH);
            g4 = kin ? ((const float4*)gamma)[(c0 >> 2) + aq] : make_float4(0, 0, 0, 0);
            b4 = kin ? ((const float4*)beta)[(c0 >> 2) + aq]  : make_float4(0, 0, 0, 0);
            #pragma unroll
            for (int r = 0; r < 8; r++) {
                int gr = rowBase + arow + r * 16;
                xr[r] = (kin && gr < N) ? ((const float4*)(x + (size_t)gr * CH))[(c0 >> 2) + aq]
                                        : make_float4(0, 0, 0, 0);
            }
            #pragma unroll
            for (int r = 0; r < 3; r++) {
                int gj = bnBase + brow + r * 32;
                bh[r] = ((const uint4*)(g_Bhi + (size_t)gj * CHP + c0))[bq];
                bl[r] = ((const uint4*)(g_Blo + (size_t)gj * CHP + c0))[bq];
            }
        }

        // ---- MMA: 4 k16 steps ----
        #pragma unroll
        for (int s = 0; s < 4; s++) {
            uint32_t ahi[2][4], alo[2][4], bhi[3][4], blo[3][4];
            uint32_t kb = (uint32_t)(s * 32 + ((lane >> 4) & 1) * 16);
            #pragma unroll
            for (int t = 0; t < 2; t++) {
                int row = wm * 32 + t * 16 + (lane & 15);
                uint32_t off = (uint32_t)(row * 128) + (kb ^ ((uint32_t)(row & 7) << 4));
                LDMX4(ahi[t][0], ahi[t][1], ahi[t][2], ahi[t][3], sAhi + off);
                LDMX4(alo[t][0], alo[t][1], alo[t][2], alo[t][3], sAlo + off);
            }
            #pragma unroll
            for (int g = 0; g < 3; g++) {
                int row = wn * 48 + g * 16 + (lane & 15);
                uint32_t off = (uint32_t)(row * 128) + (kb ^ ((uint32_t)(row & 7) << 4));
                LDMX4(bhi[g][0], bhi[g][1], bhi[g][2], bhi[g][3], sBhi + off);
                LDMX4(blo[g][0], blo[g][1], blo[g][2], blo[g][3], sBlo + off);
            }
            #pragma unroll
            for (int t = 0; t < 2; t++) {
                #pragma unroll
                for (int g = 0; g < 3; g++) {
                    #pragma unroll
                    for (int h = 0; h < 2; h++) {
                        int nt = g * 2 + h;
                        MMA16816(acc[t][nt], ahi[t], bhi[g][h], bhi[g][h + 2]);
                        MMA16816(acc[t][nt], alo[t], bhi[g][h], bhi[g][h + 2]);
                        MMA16816(acc[t][nt], ahi[t], blo[g][h], blo[g][h + 2]);
                    }
                }
            }
        }
    }

    // ---- epilogue ----
    #pragma unroll
    for (int t = 0; t < 2; t++) {
        int r0 = rowBase + wm * 32 + t * 16 + (lane >> 2);
        #pragma unroll
        for (int nt = 0; nt < 6; nt++) {
            int cc = bnBase + wn * 48 + nt * 8 + ((lane & 3) << 1);
            if (cc < JN) {
                if (r0 < N)
                    *(float2*)(sim + (size_t)r0 * JN + cc) =
                        make_float2(acc[t][nt][0], acc[t][nt][1]);
                if (r0 + 8 < N)
                    *(float2*)(sim + (size_t)(r0 + 8) * JN + cc) =
                        make_float2(acc[t][nt][2], acc[t][nt][3]);
            }
        }
    }
}

// ---------------- K3: coalesced tile kpix ----------------
// block: 256 threads, 128 pixels. smem = 128*190*4 = 97280 B.
#define KPIX_SMEM 97280
__global__ __launch_bounds__(256) void kpix(const float* __restrict__ sim,
                                            const int* __restrict__ gt,
                                            float* __restrict__ pred_out, int N) {
    extern __shared__ float srow[];   // [128][190]
    __shared__ float sS[KC];
    __shared__ int sC[KC];
    if (threadIdx.x < KC) { sS[threadIdx.x] = 0.f; sC[threadIdx.x] = 0; }
    int base = blockIdx.x * 128;
    int npix = min(128, N - base);
    if (npix <= 0) return;
    // coalesced bulk load of the contiguous [npix x 190] region
    int n4 = npix * JN / 2;  // float2 granularity (190*4 % 8 == 0)
    const float2* src = (const float2*)(sim + (size_t)base * JN);
    float2* dst = (float2*)srow;
    for (int i = threadIdx.x; i < n4; i += 256) dst[i] = src[i];
    __syncthreads();
    if (threadIdx.x < npix) {
        int n = base + threadIdx.x;
        const float* row = srow + threadIdx.x * JN;
        int g = gt[n];
        float best = -3.4e38f; int bk = 0;
        #pragma unroll
        for (int k = 0; k < KC; k++) {
            float mk = row[k];
            #pragma unroll
            for (int m = 1; m < MP; m++) mk = fmaxf(mk, row[m * KC + k]);
            if (mk > best) { best = mk; bk = k; }
        }
        pred_out[n] = (float)bk;
        float se = 0.f;
        #pragma unroll
        for (int m = 0; m < MP; m++) {
            float e = expf(row[m * KC + g] * 20.0f);
            g_e[(size_t)n * MP + m] = e;
            se += e;
        }
        atomicAdd(&sS[g], se);
        atomicAdd(&sC[g], 1);
    }
    __syncthreads();
    if (threadIdx.x < KC) {
        if (sS[threadIdx.x] != 0.f) atomicAdd(&g_S[threadIdx.x], sS[threadIdx.x]);
        if (sC[threadIdx.x] != 0)   atomicAdd(&g_cnt[threadIdx.x], sC[threadIdx.x]);
    }
}

// ---------------- sinkhorn ----------------
template<bool FIRST>
__global__ void kT(const int* __restrict__ gt, int N) {
    __shared__ float sT[JN];
    for (int j = threadIdx.x; j < JN; j += blockDim.x) sT[j] = 0.f;
    __syncthreads();
    for (int n = blockIdx.x * blockDim.x + threadIdx.x; n < N; n += gridDim.x * blockDim.x) {
        int g = gt[n];
        float c;
        if (FIRST) { c = 1.f / fmaxf(g_S[g], 1e-12f); g_c[n] = c; }
        else        c = g_c[n];
        #pragma unroll
        for (int m = 0; m < MP; m++) atomicAdd(&sT[g * MP + m], c * g_e[(size_t)n * MP + m]);
    }
    __syncthreads();
    for (int j = threadIdx.x; j < JN; j += blockDim.x)
        if (sT[j] != 0.f) atomicAdd(&g_T[j], sT[j]);
}

__global__ void kR() {
    int j = threadIdx.x;
    if (j < JN) {
        float r = g_r[j];
        float T = g_T[j];
        g_r[j] = r / (fmaxf(r * T, 1e-12f) * (float)MP);
        g_T[j] = 0.f;
    }
}

__global__ void kC(const int* __restrict__ gt, int N) {
    int n = blockIdx.x * blockDim.x + threadIdx.x;
    if (n >= N) return;
    int g = gt[n];
    float c = g_c[n];
    float V = 0.f;
    #pragma unroll
    for (int m = 0; m < MP; m++) V += g_e[(size_t)n * MP + m] * g_r[g * MP + m];
    float ns = fmaxf((float)g_cnt[g], 1.f);
    g_c[n] = c / (fmaxf(c * V, 1e-12f) * ns);
}

__global__ void kQ(const int* __restrict__ gt, float* __restrict__ qout, int N) {
    int n = blockIdx.x * blockDim.x + threadIdx.x;
    if (n >= N) return;
    int g = gt[n];
    float ns = fmaxf((float)g_cnt[g], 1.f);
    float c = g_c[n] * ns;
    size_t base = ((size_t)g * N + n) * MP;
    #pragma unroll
    for (int m = 0; m < MP; m++)
        qout[base + m] = c * g_e[(size_t)n * MP + m] * g_r[g * MP + m];
}

// ---------------- launch ----------------
extern "C" void kernel_launch(void* const* d_in, const int* in_sizes, int n_in,
                              void* d_out, int out_size) {
    const float* x     = (const float*)d_in[0];
    const int*   gt    = (const int*)d_in[1];
    const float* gamma = (const float*)d_in[2];
    const float* beta  = (const float*)d_in[3];
    const float* proto = (const float*)d_in[4];
    int N = in_sizes[0] / CH;

    float* out  = (float*)d_out;
    float* sim  = out;                          // [N, 190]  (j = m*19+k)
    float* q    = out + (size_t)N * JN;         // [K, N, M]
    float* pred = out + 2 * (size_t)N * JN;     // [N]

    cudaFuncSetAttribute(kgemm_mma, cudaFuncAttributeMaxDynamicSharedMemorySize, GEMM_SMEM);
    cudaFuncSetAttribute(kpix, cudaFuncAttributeMaxDynamicSharedMemorySize, KPIX_SMEM);

    kprotoB<<<JN + 1, 192>>>(proto);
    kstats<<<N, 256>>>(x, gamma, beta, N);
    dim3 ggrid((N + 127) / 128, 2);
    kgemm_mma<<<ggrid, 256, GEMM_SMEM>>>(x, gamma, beta, sim, N);
    kpix<<<(N + 127) / 128, 256, KPIX_SMEM>>>(sim, gt, pred, N);

    kT<true><<<256, 256>>>(gt, N);
    kR<<<1, 256>>>();
    kC<<<(N + 255) / 256, 256>>>(gt, N);

    kT<false><<<256, 256>>>(gt, N);
    kR<<<1, 256>>>();
    kC<<<(N + 255) / 256, 256>>>(gt, N);

    kT<false><<<256, 256>>>(gt, N);
    kR<<<1, 256>>>();
    kC<<<(N + 255) / 256, 256>>>(gt, N);

    cudaMemsetAsync(q, 0, (size_t)N * JN * sizeof(float));
    kQ<<<(N + 255) / 256, 256>>>(gt, q, N);
}

// round 4
// speedup vs baseline: 2.5175x; 1.3364x over previous
#include <cuda_runtime.h>
#include <cuda_bf16.h>
#include <math.h>
#include <stdint.h>

#define KC 19
#define MP 10
#define CH 720
#define CHP 768
#define JN 190
#define JP 192
#define NMAX 65536

// ---------------- scratch ----------------
__device__ __align__(256) __nv_bfloat16 g_Bhi[JP * CHP];
__device__ __align__(256) __nv_bfloat16 g_Blo[JP * CHP];
__device__ float g_mu[NMAX];
__device__ float g_P[NMAX];
__device__ float g_Q[NMAX];
__device__ float g_e[(size_t)NMAX * MP];
__device__ float g_c[NMAX];
__device__ float g_S[KC];
__device__ int   g_cnt[KC];
__device__ float g_T3[3][JN];   // per-iteration T buffers (zero-init, re-zeroed by kprotoB)

// ---------------- helpers ----------------
__device__ __forceinline__ uint32_t smem_u32(const void* p) {
    uint32_t a;
    asm("{ .reg .u64 t; cvta.to.shared.u64 t, %1; cvt.u32.u64 %0, t; }" : "=r"(a) : "l"(p));
    return a;
}
__device__ __forceinline__ float warpReduceSum(float v) {
    #pragma unroll
    for (int o = 16; o > 0; o >>= 1) v += __shfl_xor_sync(0xffffffffu, v, o);
    return v;
}
__device__ __forceinline__ float blockReduceSum(float v, float* sh) {
    __syncthreads();
    v = warpReduceSum(v);
    int lane = threadIdx.x & 31, w = threadIdx.x >> 5;
    if (lane == 0) sh[w] = v;
    __syncthreads();
    int nw = (blockDim.x + 31) >> 5;
    v = (threadIdx.x < nw) ? sh[threadIdx.x] : 0.f;
    if (w == 0) { v = warpReduceSum(v); if (lane == 0) sh[0] = v; }
    __syncthreads();
    return sh[0];
}
// packed split: 2 fp32 -> hi bf16x2 + lo bf16x2
__device__ __forceinline__ void split2p(float a0, float a1, unsigned& h, unsigned& l) {
    unsigned hp;
    asm("cvt.rn.bf16x2.f32 %0, %1, %2;" : "=r"(hp) : "f"(a1), "f"(a0));
    float h0 = __uint_as_float(hp << 16);
    float h1 = __uint_as_float(hp & 0xffff0000u);
    unsigned lp;
    asm("cvt.rn.bf16x2.f32 %0, %1, %2;" : "=r"(lp) : "f"(a1 - h1), "f"(a0 - h0));
    h = hp; l = lp;
}
__device__ __forceinline__ void split2(float a0, float a1, unsigned& h, unsigned& l) {
    split2p(a0, a1, h, l);
}

#define LDMX4(r0, r1, r2, r3, addr) \
    asm volatile("ldmatrix.sync.aligned.m8n8.x4.shared.b16 {%0,%1,%2,%3}, [%4];" \
                 : "=r"(r0), "=r"(r1), "=r"(r2), "=r"(r3) : "r"(addr))

#define MMA16816(d, a, b0, b1) \
    asm volatile("mma.sync.aligned.m16n8k16.row.col.f32.bf16.bf16.f32 " \
                 "{%0,%1,%2,%3}, {%4,%5,%6,%7}, {%8,%9}, {%0,%1,%2,%3};" \
                 : "+f"((d)[0]), "+f"((d)[1]), "+f"((d)[2]), "+f"((d)[3]) \
                 : "r"((a)[0]), "r"((a)[1]), "r"((a)[2]), "r"((a)[3]), "r"(b0), "r"(b1))

#define CP_ASYNC16(dst, src) \
    asm volatile("cp.async.ca.shared.global [%0], [%1], 16;" \
                 :: "r"(dst), "l"(src) : "memory")

// ---------------- K0: warp-per-row stats ----------------
__global__ __launch_bounds__(256) void kstats(const float* __restrict__ x,
                                              const float* __restrict__ gamma,
                                              const float* __restrict__ beta, int N) {
    int warp = threadIdx.x >> 5, lane = threadIdx.x & 31;
    int n = blockIdx.x * 8 + warp;
    if (n >= N) return;
    const float4* xr = (const float4*)(x + (size_t)n * CH);
    float4 v[6];
    float s = 0.f, sq = 0.f;
    #pragma unroll
    for (int i = 0; i < 6; i++) {
        int idx = i * 32 + lane;
        if (idx < 180) {
            v[i] = xr[idx];
            s += v[i].x + v[i].y + v[i].z + v[i].w;
            sq += v[i].x * v[i].x + v[i].y * v[i].y + v[i].z * v[i].z + v[i].w * v[i].w;
        } else v[i] = make_float4(0, 0, 0, 0);
    }
    s = warpReduceSum(s);
    sq = warpReduceSum(sq);
    float mu = s * (1.f / (float)CH);
    float rs = rsqrtf(sq * (1.f / (float)CH) - mu * mu + 1e-5f);
    float yn = 0.f;
    #pragma unroll
    for (int i = 0; i < 6; i++) {
        int idx = i * 32 + lane;
        if (idx < 180) {
            float4 g4 = ((const float4*)gamma)[idx];
            float4 b4 = ((const float4*)beta)[idx];
            float a = (v[i].x - mu) * rs * g4.x + b4.x;
            float b = (v[i].y - mu) * rs * g4.y + b4.y;
            float c = (v[i].z - mu) * rs * g4.z + b4.z;
            float d = (v[i].w - mu) * rs * g4.w + b4.w;
            yn += a * a + b * b + c * c + d * d;
        }
    }
    yn = warpReduceSum(yn);
    float inv = 1.f / fmaxf(sqrtf(yn), 1e-12f);
    if (lane == 0) { g_mu[n] = mu; g_P[n] = rs * inv; g_Q[n] = inv; }
}

// ---------------- K1: normalize prototypes + init ----------------
__global__ __launch_bounds__(192) void kprotoB(const float* __restrict__ proto) {
    int p = blockIdx.x;
    int t = threadIdx.x;
    __shared__ float sh[32];
    if (p == JN) {
        ((uint2*)(g_Bhi + (size_t)190 * CHP))[t] = make_uint2(0u, 0u);
        ((uint2*)(g_Bhi + (size_t)191 * CHP))[t] = make_uint2(0u, 0u);
        ((uint2*)(g_Blo + (size_t)190 * CHP))[t] = make_uint2(0u, 0u);
        ((uint2*)(g_Blo + (size_t)191 * CHP))[t] = make_uint2(0u, 0u);
        if (t < KC) { g_S[t] = 0.f; g_cnt[t] = 0; }
        for (int j = t; j < 3 * JN; j += 192) ((float*)g_T3)[j] = 0.f;
        return;
    }
    int k = p / MP, m = p % MP;
    int j = m * KC + k;
    const float4* pr = (const float4*)(proto + (size_t)p * CH);
    float4 v = make_float4(0, 0, 0, 0);
    float ss = 0.f;
    if (t < 180) {
        v = pr[t];
        ss = v.x * v.x + v.y * v.y + v.z * v.z + v.w * v.w;
    }
    ss = blockReduceSum(ss, sh);
    float inv = 1.f / fmaxf(sqrtf(ss), 1e-12f);
    uint2 h = make_uint2(0u, 0u), l = make_uint2(0u, 0u);
    if (t < 180) {
        split2(v.x * inv, v.y * inv, h.x, l.x);
        split2(v.z * inv, v.w * inv, h.y, l.y);
    }
    ((uint2*)(g_Bhi + (size_t)j * CHP))[t] = h;
    ((uint2*)(g_Blo + (size_t)j * CHP))[t] = l;
}

// ---------------- K2: HMMA GEMM 128x192, fused conversion, 2-stage ----------------
// 512 threads = 16 warps = 4M x 4N, warp tile 32x48.
// Stage: Ahi 16K @0, Alo 16K @16K, Bhi 24K @32K, Blo 24K @56K  => 80K, x2 stages
#define STG 81920
#define GEMM_SMEM (2 * STG)

__global__ __launch_bounds__(512, 1) void kgemm_mma(const float* __restrict__ x,
                                                    const float* __restrict__ gamma,
                                                    const float* __restrict__ beta,
                                                    float* __restrict__ sim, int N) {
    extern __shared__ char smem[];
    const uint32_t sb = smem_u32(smem);

    int tid = threadIdx.x;
    int lane = tid & 31, warp = tid >> 5;
    int wm = warp & 3, wn = warp >> 2;
    int rowBase = (int)blockIdx.x * 128;

    int arow = tid >> 4, aq = tid & 15;     // A: rows arow + r*32 (r<4), float4 col aq
    int brow = tid >> 3, bq = tid & 7;      // B: rows brow + r*64 (r<3), uint4 col bq

    float mu[4], Pv[4], Qv[4];
    #pragma unroll
    for (int r = 0; r < 4; r++) {
        int gr = rowBase + arow + r * 32;
        if (gr < N) { mu[r] = g_mu[gr]; Pv[r] = g_P[gr]; Qv[r] = g_Q[gr]; }
        else        { mu[r] = 0.f; Pv[r] = 0.f; Qv[r] = 0.f; }
    }

    float acc[2][6][4];
    #pragma unroll
    for (int t = 0; t < 2; t++)
        #pragma unroll
        for (int nt = 0; nt < 6; nt++)
            #pragma unroll
            for (int i = 0; i < 4; i++) acc[t][nt][i] = 0.f;

    float4 xr[4], g4, b4;

    // ---- prologue: prefetch chunk 0 (A regs + B cp.async -> stage 0) ----
    {
        g4 = ((const float4*)gamma)[aq];
        b4 = ((const float4*)beta)[aq];
        #pragma unroll
        for (int r = 0; r < 4; r++) {
            int gr = rowBase + arow + r * 32;
            xr[r] = (gr < N) ? ((const float4*)(x + (size_t)gr * CH))[aq]
                             : make_float4(0, 0, 0, 0);
        }
        uint32_t sBhi = sb + 32768, sBlo = sb + 57344;
        #pragma unroll
        for (int r = 0; r < 3; r++) {
            int row = brow + r * 64;
            uint32_t off = (uint32_t)(row * 128 + ((bq * 16) ^ ((row & 7) << 4)));
            CP_ASYNC16(sBhi + off, (const char*)(g_Bhi + (size_t)row * CHP) + bq * 16);
            CP_ASYNC16(sBlo + off, (const char*)(g_Blo + (size_t)row * CHP) + bq * 16);
        }
        asm volatile("cp.async.commit_group;" ::: "memory");
    }

    for (int c = 0; c < 12; c++) {
        uint32_t st = sb + (uint32_t)(c & 1) * STG;
        uint32_t sAhi = st, sAlo = st + 16384, sBhi = st + 32768, sBlo = st + 57344;

        // ---- convert + store A(c) ----
        #pragma unroll
        for (int r = 0; r < 4; r++) {
            float a1x = Pv[r] * g4.x, a1y = Pv[r] * g4.y, a1z = Pv[r] * g4.z, a1w = Pv[r] * g4.w;
            float yx = (xr[r].x - mu[r]) * a1x + Qv[r] * b4.x;
            float yy = (xr[r].y - mu[r]) * a1y + Qv[r] * b4.y;
            float yz = (xr[r].z - mu[r]) * a1z + Qv[r] * b4.z;
            float yw = (xr[r].w - mu[r]) * a1w + Qv[r] * b4.w;
            unsigned h0, l0, h1, l1;
            split2p(yx, yy, h0, l0);
            split2p(yz, yw, h1, l1);
            int row = arow + r * 32;
            uint32_t off = (uint32_t)(row * 128 + ((aq * 8) ^ ((row & 7) << 4)));
            asm volatile("st.shared.v2.b32 [%0], {%1,%2};" :: "r"(sAhi + off), "r"(h0), "r"(h1));
            asm volatile("st.shared.v2.b32 [%0], {%1,%2};" :: "r"(sAlo + off), "r"(l0), "r"(l1));
        }
        asm volatile("cp.async.wait_group 0;" ::: "memory");
        __syncthreads();

        // ---- prefetch chunk c+1 into regs / other stage ----
        if (c < 11) {
            int c0 = (c + 1) * 64;
            bool kin = (c0 + aq * 4) < CH;
            g4 = kin ? ((const float4*)gamma)[(c0 >> 2) + aq] : make_float4(0, 0, 0, 0);
            b4 = kin ? ((const float4*)beta)[(c0 >> 2) + aq]  : make_float4(0, 0, 0, 0);
            #pragma unroll
            for (int r = 0; r < 4; r++) {
                int gr = rowBase + arow + r * 32;
                xr[r] = (kin && gr < N) ? ((const float4*)(x + (size_t)gr * CH))[(c0 >> 2) + aq]
                                        : make_float4(0, 0, 0, 0);
            }
            uint32_t st2 = sb + (uint32_t)((c + 1) & 1) * STG;
            uint32_t nBhi = st2 + 32768, nBlo = st2 + 57344;
            #pragma unroll
            for (int r = 0; r < 3; r++) {
                int row = brow + r * 64;
                uint32_t off = (uint32_t)(row * 128 + ((bq * 16) ^ ((row & 7) << 4)));
                CP_ASYNC16(nBhi + off, (const char*)(g_Bhi + (size_t)row * CHP + c0) + bq * 16);
                CP_ASYNC16(nBlo + off, (const char*)(g_Blo + (size_t)row * CHP + c0) + bq * 16);
            }
            asm volatile("cp.async.commit_group;" ::: "memory");
        }

        // ---- MMA on stage c&1 ----
        #pragma unroll
        for (int s = 0; s < 4; s++) {
            uint32_t ahi[2][4], alo[2][4], bhi[3][4], blo[3][4];
            uint32_t kb = (uint32_t)(s * 32 + ((lane >> 4) & 1) * 16);
            #pragma unroll
            for (int t = 0; t < 2; t++) {
                int row = wm * 32 + t * 16 + (lane & 15);
                uint32_t off = (uint32_t)(row * 128) + (kb ^ ((uint32_t)(row & 7) << 4));
                LDMX4(ahi[t][0], ahi[t][1], ahi[t][2], ahi[t][3], sAhi + off);
                LDMX4(alo[t][0], alo[t][1], alo[t][2], alo[t][3], sAlo + off);
            }
            #pragma unroll
            for (int g = 0; g < 3; g++) {
                int row = wn * 48 + g * 16 + (lane & 15);
                uint32_t off = (uint32_t)(row * 128) + (kb ^ ((uint32_t)(row & 7) << 4));
                LDMX4(bhi[g][0], bhi[g][1], bhi[g][2], bhi[g][3], sBhi + off);
                LDMX4(blo[g][0], blo[g][1], blo[g][2], blo[g][3], sBlo + off);
            }
            #pragma unroll
            for (int t = 0; t < 2; t++)
                #pragma unroll
                for (int g = 0; g < 3; g++)
                    #pragma unroll
                    for (int h = 0; h < 2; h++) {
                        int nt = g * 2 + h;
                        MMA16816(acc[t][nt], ahi[t], bhi[g][h], bhi[g][h + 2]);
                        MMA16816(acc[t][nt], alo[t], bhi[g][h], bhi[g][h + 2]);
                        MMA16816(acc[t][nt], ahi[t], blo[g][h], blo[g][h + 2]);
                    }
        }
    }

    // ---- epilogue ----
    #pragma unroll
    for (int t = 0; t < 2; t++) {
        int r0 = rowBase + wm * 32 + t * 16 + (lane >> 2);
        #pragma unroll
        for (int nt = 0; nt < 6; nt++) {
            int cc = wn * 48 + nt * 8 + ((lane & 3) << 1);
            if (cc < JN) {
                if (r0 < N)
                    *(float2*)(sim + (size_t)r0 * JN + cc) =
                        make_float2(acc[t][nt][0], acc[t][nt][1]);
                if (r0 + 8 < N)
                    *(float2*)(sim + (size_t)(r0 + 8) * JN + cc) =
                        make_float2(acc[t][nt][2], acc[t][nt][3]);
            }
        }
    }
}

// ---------------- K3: kpix, 64 pixels / 128 threads ----------------
#define KPIX_SMEM (64 * JN * 4)
__global__ __launch_bounds__(128) void kpix(const float* __restrict__ sim,
                                            const int* __restrict__ gt,
                                            float* __restrict__ pred_out, int N) {
    extern __shared__ float srow[];   // [64][190]
    __shared__ float sS[KC];
    __shared__ int sC[KC];
    if (threadIdx.x < KC) { sS[threadIdx.x] = 0.f; sC[threadIdx.x] = 0; }
    int base = blockIdx.x * 64;
    int npix = min(64, N - base);
    if (npix <= 0) return;
    int n4 = npix * JN / 2;
    const float2* src = (const float2*)(sim + (size_t)base * JN);
    float2* dst = (float2*)srow;
    for (int i = threadIdx.x; i < n4; i += 128) dst[i] = src[i];
    __syncthreads();
    if (threadIdx.x < npix) {
        int n = base + threadIdx.x;
        const float* row = srow + threadIdx.x * JN;
        int g = gt[n];
        float best = -3.4e38f; int bk = 0;
        #pragma unroll
        for (int k = 0; k < KC; k++) {
            float mk = row[k];
            #pragma unroll
            for (int m = 1; m < MP; m++) mk = fmaxf(mk, row[m * KC + k]);
            if (mk > best) { best = mk; bk = k; }
        }
        pred_out[n] = (float)bk;
        float se = 0.f;
        #pragma unroll
        for (int m = 0; m < MP; m++) {
            float e = expf(row[m * KC + g] * 20.0f);
            g_e[(size_t)n * MP + m] = e;
            se += e;
        }
        atomicAdd(&sS[g], se);
        atomicAdd(&sC[g], 1);
    }
    __syncthreads();
    if (threadIdx.x < KC) {
        if (sS[threadIdx.x] != 0.f) atomicAdd(&g_S[threadIdx.x], sS[threadIdx.x]);
        if (sC[threadIdx.x] != 0)   atomicAdd(&g_cnt[threadIdx.x], sC[threadIdx.x]);
    }
}

// ---------------- sinkhorn ----------------
template<int IT>
__global__ void kT(const int* __restrict__ gt, int N) {
    __shared__ float sT[JN];
    for (int j = threadIdx.x; j < JN; j += blockDim.x) sT[j] = 0.f;
    __syncthreads();
    int n = blockIdx.x * blockDim.x + threadIdx.x;
    if (n < N) {
        int g = gt[n];
        float c;
        if (IT == 0) { c = 1.f / fmaxf(g_S[g], 1e-12f); g_c[n] = c; }
        else          c = g_c[n];
        #pragma unroll
        for (int m = 0; m < MP; m++) atomicAdd(&sT[g * MP + m], c * g_e[(size_t)n * MP + m]);
    }
    __syncthreads();
    for (int j = threadIdx.x; j < JN; j += blockDim.x)
        if (sT[j] != 0.f) atomicAdd(&g_T3[IT][j], sT[j]);
}

// recompute r-chain through iteration IT, then update c
template<int IT>
__global__ void kC(const int* __restrict__ gt, int N) {
    __shared__ float sr[JN];
    if (threadIdx.x < JN) {
        float r = 1.f;
        #pragma unroll
        for (int it = 0; it <= IT; it++)
            r = r / (fmaxf(r * g_T3[it][threadIdx.x], 1e-12f) * (float)MP);
        sr[threadIdx.x] = r;
    }
    __syncthreads();
    int n = blockIdx.x * blockDim.x + threadIdx.x;
    if (n >= N) return;
    int g = gt[n];
    float c = g_c[n];
    float V = 0.f;
    #pragma unroll
    for (int m = 0; m < MP; m++) V += g_e[(size_t)n * MP + m] * sr[g * MP + m];
    float ns = fmaxf((float)g_cnt[g], 1.f);
    g_c[n] = c / (fmaxf(c * V, 1e-12f) * ns);
}

// final: c update for iter 3 fused with q scatter
__global__ void kCQ(const int* __restrict__ gt, float* __restrict__ qout, int N) {
    __shared__ float sr[JN];
    if (threadIdx.x < JN) {
        float r = 1.f;
        #pragma unroll
        for (int it = 0; it < 3; it++)
            r = r / (fmaxf(r * g_T3[it][threadIdx.x], 1e-12f) * (float)MP);
        sr[threadIdx.x] = r;
    }
    __syncthreads();
    int n = blockIdx.x * blockDim.x + threadIdx.x;
    if (n >= N) return;
    int g = gt[n];
    float c = g_c[n];
    float e[MP], V = 0.f;
    #pragma unroll
    for (int m = 0; m < MP; m++) { e[m] = g_e[(size_t)n * MP + m]; V += e[m] * sr[g * MP + m]; }
    float ns = fmaxf((float)g_cnt[g], 1.f);
    c = c / (fmaxf(c * V, 1e-12f) * ns);        // c3
    float cs = c * ns;
    size_t base = ((size_t)g * N + n) * MP;
    #pragma unroll
    for (int m = 0; m < MP; m++)
        qout[base + m] = cs * e[m] * sr[g * MP + m];
}

// ---------------- launch ----------------
extern "C" void kernel_launch(void* const* d_in, const int* in_sizes, int n_in,
                              void* d_out, int out_size) {
    const float* x     = (const float*)d_in[0];
    const int*   gt    = (const int*)d_in[1];
    const float* gamma = (const float*)d_in[2];
    const float* beta  = (const float*)d_in[3];
    const float* proto = (const float*)d_in[4];
    int N = in_sizes[0] / CH;

    float* out  = (float*)d_out;
    float* sim  = out;
    float* q    = out + (size_t)N * JN;
    float* pred = out + 2 * (size_t)N * JN;

    cudaFuncSetAttribute(kgemm_mma, cudaFuncAttributeMaxDynamicSharedMemorySize, GEMM_SMEM);
    cudaFuncSetAttribute(kpix, cudaFuncAttributeMaxDynamicSharedMemorySize, KPIX_SMEM);

    kprotoB<<<JN + 1, 192>>>(proto);
    kstats<<<(N + 7) / 8, 256>>>(x, gamma, beta, N);
    kgemm_mma<<<(N + 127) / 128, 512, GEMM_SMEM>>>(x, gamma, beta, sim, N);
    kpix<<<(N + 63) / 64, 128, KPIX_SMEM>>>(sim, gt, pred, N);

    kT<0><<<(N + 255) / 256, 256>>>(gt, N);
    kC<0><<<(N + 255) / 256, 256>>>(gt, N);
    kT<1><<<(N + 255) / 256, 256>>>(gt, N);
    kC<1><<<(N + 255) / 256, 256>>>(gt, N);
    kT<2><<<(N + 255) / 256, 256>>>(gt, N);

    cudaMemsetAsync(q, 0, (size_t)N * JN * sizeof(float));
    kCQ<<<(N + 255) / 256, 256>>>(gt, q, N);
}